// round 1
// baseline (speedup 1.0000x reference)
#include <cuda_runtime.h>
#include <cuda_bf16.h>
#include <math_constants.h>

// Problem constants
#define B_   16
#define S_   2048
#define D_   512
#define C_   8192

// GEMM tiling
#define BM 128
#define BN 128
#define BK 8
#define TM 8
#define TN 8
#define NTHREADS 256

// 0.5 * ||embed[c]||^2, precomputed each launch (deterministic)
__device__ float g_e2h[C_];

// ---------------------------------------------------------------------------
// Kernel 1: e2h[c] = 0.5 * sum_d embed[c][d]^2   (one warp per code)
// ---------------------------------------------------------------------------
__global__ void e2_kernel(const float* __restrict__ embed) {
    int warp = threadIdx.x >> 5;
    int lane = threadIdx.x & 31;
    int c = blockIdx.x * 8 + warp;
    if (c >= C_) return;
    const float4* row = reinterpret_cast<const float4*>(embed + (size_t)c * D_);
    float s = 0.f;
    #pragma unroll
    for (int i = lane; i < D_ / 4; i += 32) {
        float4 v = row[i];
        s += v.x * v.x + v.y * v.y + v.z * v.z + v.w * v.w;
    }
    #pragma unroll
    for (int o = 16; o > 0; o >>= 1) s += __shfl_xor_sync(0xffffffffu, s, o);
    if (lane == 0) g_e2h[c] = 0.5f * s;
}

// ---------------------------------------------------------------------------
// Kernel 2: fused GEMM + streaming argmax + gather + mask
// Each block: BM=128 consecutive tokens of one batch, loops over all C codes.
// ---------------------------------------------------------------------------
__global__ void __launch_bounds__(NTHREADS)
vq_kernel(const float* __restrict__ x,
          const int*   __restrict__ input_length,
          const float* __restrict__ embed,
          float*       __restrict__ out)
{
    __shared__ float As[2][BK][BM];
    __shared__ float Bs[2][BK][BN];
    __shared__ float sVal[BM][17];   // padded: conflict-free column scans
    __shared__ int   sInd[BM][17];
    __shared__ int   sIdx[BM];

    const int tid   = threadIdx.x;
    const int bt    = blockIdx.x;              // 0 .. B*S/BM-1
    const int TILES = S_ / BM;                 // 16 tiles per batch
    const int batch = bt / TILES;
    const int tile  = bt % TILES;
    const int token0 = batch * S_ + tile * BM;

    const int len = input_length[batch];
    int active = len - tile * BM;
    active = active < 0 ? 0 : (active > BM ? BM : active);

    float* outq = out;                              // [B*S, D] quantize
    float* outi = out + (size_t)B_ * S_ * D_;       // [B*S]   embed_ind (as f32)

    if (active == 0) {
        // whole tile masked: zeros + (-1), skip all compute
        float4 z = make_float4(0.f, 0.f, 0.f, 0.f);
        float4* q = reinterpret_cast<float4*>(outq + (size_t)token0 * D_);
        for (int i = tid; i < BM * (D_ / 4); i += NTHREADS) q[i] = z;
        if (tid < BM) outi[token0 + tid] = -1.0f;
        return;
    }

    // --- thread mapping -----------------------------------------------------
    const int ty = tid >> 4;        // 0..15 -> row group (TM rows)
    const int tx = tid & 15;        // 0..15 -> col group (TN cols)

    // loader mapping: pairs of threads cover one row (32B contiguous each pair)
    const int lrow = tid >> 1;      // 0..127
    const int lkq  = (tid & 1) * 4; // 0 or 4 (which half of BK=8)

    const float* xbase = x + (size_t)(token0 + lrow) * D_ + lkq;

    float best_val[TM];
    int   best_idx[TM];
    #pragma unroll
    for (int i = 0; i < TM; i++) { best_val[i] = -CUDART_INF_F; best_idx[i] = 0; }

    const int NKB = D_ / BK;        // 64

    for (int c0 = 0; c0 < C_; c0 += BN) {
        const float* ebase = embed + (size_t)(c0 + lrow) * D_ + lkq;

        // preload kb=0 into buffer 0
        float4 a = *reinterpret_cast<const float4*>(xbase);
        float4 b = *reinterpret_cast<const float4*>(ebase);
        As[0][lkq + 0][lrow] = a.x; As[0][lkq + 1][lrow] = a.y;
        As[0][lkq + 2][lrow] = a.z; As[0][lkq + 3][lrow] = a.w;
        Bs[0][lkq + 0][lrow] = b.x; Bs[0][lkq + 1][lrow] = b.y;
        Bs[0][lkq + 2][lrow] = b.z; Bs[0][lkq + 3][lrow] = b.w;
        __syncthreads();

        float acc[TM][TN];
        #pragma unroll
        for (int i = 0; i < TM; i++)
            #pragma unroll
            for (int j = 0; j < TN; j++) acc[i][j] = 0.f;

        int p = 0;
        for (int kb = 0; kb < NKB; ++kb) {
            // prefetch next K-slab into registers (latency hidden by compute)
            if (kb + 1 < NKB) {
                a = *reinterpret_cast<const float4*>(xbase + (kb + 1) * BK);
                b = *reinterpret_cast<const float4*>(ebase + (kb + 1) * BK);
            }
            #pragma unroll
            for (int k = 0; k < BK; k++) {
                float4 a0 = *reinterpret_cast<const float4*>(&As[p][k][ty * TM]);
                float4 a1 = *reinterpret_cast<const float4*>(&As[p][k][ty * TM + 4]);
                float4 b0 = *reinterpret_cast<const float4*>(&Bs[p][k][tx * TN]);
                float4 b1 = *reinterpret_cast<const float4*>(&Bs[p][k][tx * TN + 4]);
                float av[TM] = {a0.x, a0.y, a0.z, a0.w, a1.x, a1.y, a1.z, a1.w};
                float bv[TN] = {b0.x, b0.y, b0.z, b0.w, b1.x, b1.y, b1.z, b1.w};
                #pragma unroll
                for (int i = 0; i < TM; i++)
                    #pragma unroll
                    for (int j = 0; j < TN; j++)
                        acc[i][j] = fmaf(av[i], bv[j], acc[i][j]);
            }
            if (kb + 1 < NKB) {
                int q = 1 - p;
                As[q][lkq + 0][lrow] = a.x; As[q][lkq + 1][lrow] = a.y;
                As[q][lkq + 2][lrow] = a.z; As[q][lkq + 3][lrow] = a.w;
                Bs[q][lkq + 0][lrow] = b.x; Bs[q][lkq + 1][lrow] = b.y;
                Bs[q][lkq + 2][lrow] = b.z; Bs[q][lkq + 3][lrow] = b.w;
            }
            __syncthreads();
            p ^= 1;
        }

        // score = dot - 0.5*||e||^2 ; running best per row.
        // Within a thread, codes are strictly ascending across chunks, so
        // strict ">" keeps the earliest (lowest) index on exact ties.
        #pragma unroll
        for (int j = 0; j < TN; j++) {
            int code = c0 + tx * TN + j;
            float e2h = g_e2h[code];
            #pragma unroll
            for (int i = 0; i < TM; i++) {
                float s = acc[i][j] - e2h;
                if (s > best_val[i]) { best_val[i] = s; best_idx[i] = code; }
            }
        }
    }

    // --- block-wide argmax reduction (16 candidates per row) ----------------
    #pragma unroll
    for (int i = 0; i < TM; i++) {
        sVal[ty * TM + i][tx] = best_val[i];
        sInd[ty * TM + i][tx] = best_idx[i];
    }
    __syncthreads();

    if (tid < BM) {
        float bv = sVal[tid][0];
        int   bi = sInd[tid][0];
        #pragma unroll
        for (int t = 1; t < 16; t++) {
            float v = sVal[tid][t];
            int   ii = sInd[tid][t];
            if (v > bv || (v == bv && ii < bi)) { bv = v; bi = ii; }
        }
        sIdx[tid] = bi;
        outi[token0 + tid] = (tid < active) ? (float)bi : -1.0f;
    }
    __syncthreads();

    // --- gather embed[best] (or zeros for masked rows) -----------------------
    float4* q = reinterpret_cast<float4*>(outq + (size_t)token0 * D_);
    const float4 z = make_float4(0.f, 0.f, 0.f, 0.f);
    for (int v = tid; v < BM * (D_ / 4); v += NTHREADS) {
        int r  = v >> 7;        // D_/4 = 128
        int dc = v & 127;
        float4 val = z;
        if (r < active) {
            val = reinterpret_cast<const float4*>(embed + (size_t)sIdx[r] * D_)[dc];
        }
        q[v] = val;
        (void)dc;
    }
}

// ---------------------------------------------------------------------------
extern "C" void kernel_launch(void* const* d_in, const int* in_sizes, int n_in,
                              void* d_out, int out_size)
{
    const float* x     = (const float*)d_in[0];   // [B,S,D] f32
    const int*   ilen  = (const int*)  d_in[1];   // [B]     i32
    const float* embed = (const float*)d_in[2];   // [C,D]   f32
    float* out = (float*)d_out;                   // quantize [B,S,D] then ind [B,S]

    e2_kernel<<<C_ / 8, 256>>>(embed);
    vq_kernel<<<(B_ * S_) / BM, NTHREADS>>>(x, ilen, embed, out);
}